// round 5
// baseline (speedup 1.0000x reference)
#include <cuda_runtime.h>
#include <cuda_bf16.h>

// ============================================================================
// MaskFunctionHaar fused kernel, v2.1.
// Output depends only on M = floor(t*1024) in [0,1024) (Haar edges are exact
// fp32 multiples of 2^-10). Each block builds the 1024-entry float4 LUT in
// SMEM (thread tid owns M = 2*tid, 2*tid+1; levels 0..8 shared as partial P,
// level 9 row R gives h1 = P +/- R; both MLP tails evaluated jointly sharing
// every W2/W3 SMEM read), then each thread gathers one float4 of t.
// ============================================================================

__global__ __launch_bounds__(512, 1) void haar_fused2_kernel(
    const float4* __restrict__ t4,
    const float* __restrict__ W1, const float* __restrict__ b1,
    const float* __restrict__ W2, const float* __restrict__ b2,
    const float* __restrict__ W3, const float* __restrict__ b3,
    float4* __restrict__ out4, int n4) {
    __shared__ float4 lut[1024];     // 16 KB
    __shared__ float4 sW2v[16];      // W2 rows, 2 float4 per row
    __shared__ float4 sW3v[8];       // W3 rows padded to float4
    __shared__ float  sb1[8];
    __shared__ float4 sb2v[2];
    __shared__ float4 sb3v;
    __shared__ float  w3raw[24];

    const int tid = threadIdx.x;
    const int g   = blockIdx.x * 512 + tid;

    // prefetch this thread's t values (hide DRAM latency under LUT build)
    float4 tv = (g < n4) ? __ldg(t4 + g) : make_float4(0.f, 0.f, 0.f, 0.f);

    // ---- stage weights into SMEM ----
    if (tid < 16) {
        sW2v[tid] = __ldg((const float4*)W2 + tid);
    } else if (tid < 40) {               // W3: 24 coalesced scalar loads
        w3raw[tid - 16] = __ldg(W3 + (tid - 16));
    } else if (tid < 48) {
        sb1[tid - 40] = __ldg(b1 + (tid - 40));
    } else if (tid < 56) {
        ((float*)sb2v)[tid - 48] = __ldg(b2 + (tid - 48));
    } else if (tid < 59) {
        ((float*)&sb3v)[tid - 56] = __ldg(b3 + (tid - 56));
    } else if (tid == 59) {
        ((float*)&sb3v)[3] = 0.0f;
    }
    __syncthreads();
    if (tid < 8) {                        // repack W3 rows into padded float4
        sW3v[tid] = make_float4(w3raw[tid * 3], w3raw[tid * 3 + 1],
                                w3raw[tid * 3 + 2], 0.0f);
    }
    __syncthreads();

    // ---- layer 1 partial: levels 0..8 (shared by M = 2*tid and 2*tid+1) ----
    float P[8];
#pragma unroll
    for (int h = 0; h < 8; ++h) P[h] = sb1[h];

#pragma unroll
    for (int j = 0; j < 9; ++j) {
        int idx = (1 << j) - 1 + (tid >> (9 - j));
        float s = ((tid >> (8 - j)) & 1) ? -1.0f : 1.0f;
        const float4* row = (const float4*)(W1 + idx * 8);
        float4 a = __ldg(row);
        float4 c = __ldg(row + 1);
        P[0] = fmaf(s, a.x, P[0]); P[1] = fmaf(s, a.y, P[1]);
        P[2] = fmaf(s, a.z, P[2]); P[3] = fmaf(s, a.w, P[3]);
        P[4] = fmaf(s, c.x, P[4]); P[5] = fmaf(s, c.y, P[5]);
        P[6] = fmaf(s, c.z, P[6]); P[7] = fmaf(s, c.w, P[7]);
    }

    // level 9: row 511 + tid; eval0 (M = 2*tid): +R, eval1 (M = 2*tid+1): -R
    const float4* r9 = (const float4*)(W1 + (511 + tid) * 8);
    float4 a9 = __ldg(r9), c9 = __ldg(r9 + 1);
    float R[8] = {a9.x, a9.y, a9.z, a9.w, c9.x, c9.y, c9.z, c9.w};

    float h1a[8], h1b[8];
#pragma unroll
    for (int h = 0; h < 8; ++h) {
        h1a[h] = fmaxf(P[h] + R[h], 0.0f);
        h1b[h] = fmaxf(P[h] - R[h], 0.0f);
    }

    // ---- layer 2 (joint): each W2 element read once, used for both evals ----
    float h2a[8], h2b[8];
    {
        float4 bb0 = sb2v[0], bb1 = sb2v[1];
        h2a[0] = bb0.x; h2a[1] = bb0.y; h2a[2] = bb0.z; h2a[3] = bb0.w;
        h2a[4] = bb1.x; h2a[5] = bb1.y; h2a[6] = bb1.z; h2a[7] = bb1.w;
#pragma unroll
        for (int k = 0; k < 8; ++k) h2b[k] = h2a[k];
    }
#pragma unroll
    for (int h = 0; h < 8; ++h) {
        float4 w0 = sW2v[2 * h];
        float4 w1 = sW2v[2 * h + 1];
        float xa = h1a[h], xb = h1b[h];
        h2a[0] = fmaf(xa, w0.x, h2a[0]); h2b[0] = fmaf(xb, w0.x, h2b[0]);
        h2a[1] = fmaf(xa, w0.y, h2a[1]); h2b[1] = fmaf(xb, w0.y, h2b[1]);
        h2a[2] = fmaf(xa, w0.z, h2a[2]); h2b[2] = fmaf(xb, w0.z, h2b[2]);
        h2a[3] = fmaf(xa, w0.w, h2a[3]); h2b[3] = fmaf(xb, w0.w, h2b[3]);
        h2a[4] = fmaf(xa, w1.x, h2a[4]); h2b[4] = fmaf(xb, w1.x, h2b[4]);
        h2a[5] = fmaf(xa, w1.y, h2a[5]); h2b[5] = fmaf(xb, w1.y, h2b[5]);
        h2a[6] = fmaf(xa, w1.z, h2a[6]); h2b[6] = fmaf(xb, w1.z, h2b[6]);
        h2a[7] = fmaf(xa, w1.w, h2a[7]); h2b[7] = fmaf(xb, w1.w, h2b[7]);
    }
#pragma unroll
    for (int k = 0; k < 8; ++k) {
        h2a[k] = fmaxf(h2a[k], 0.0f);
        h2b[k] = fmaxf(h2b[k], 0.0f);
    }

    // ---- layer 3 (joint) ----
    float4 oa = sb3v, ob = sb3v;
#pragma unroll
    for (int k = 0; k < 8; ++k) {
        float4 w = sW3v[k];
        float xa = h2a[k], xb = h2b[k];
        oa.x = fmaf(xa, w.x, oa.x); ob.x = fmaf(xb, w.x, ob.x);
        oa.y = fmaf(xa, w.y, oa.y); ob.y = fmaf(xb, w.y, ob.y);
        oa.z = fmaf(xa, w.z, oa.z); ob.z = fmaf(xb, w.z, ob.z);
    }
    oa.w = 0.0f; ob.w = 0.0f;
    lut[2 * tid]     = oa;
    lut[2 * tid + 1] = ob;

    __syncthreads();

    // ---- gather: one float4 of t -> 4 SMEM lookups -> 3 float4 stores ----
    if (g < n4) {
        unsigned m0 = min((unsigned)(int)(tv.x * 1024.0f), 1023u);
        unsigned m1 = min((unsigned)(int)(tv.y * 1024.0f), 1023u);
        unsigned m2 = min((unsigned)(int)(tv.z * 1024.0f), 1023u);
        unsigned m3 = min((unsigned)(int)(tv.w * 1024.0f), 1023u);

        float4 r0 = lut[m0];
        float4 r1 = lut[m1];
        float4 r2 = lut[m2];
        float4 r3 = lut[m3];

        out4[g * 3 + 0] = make_float4(r0.x, r0.y, r0.z, r1.x);
        out4[g * 3 + 1] = make_float4(r1.y, r1.z, r2.x, r2.y);
        out4[g * 3 + 2] = make_float4(r2.z, r3.x, r3.y, r3.z);
    }
}

extern "C" void kernel_launch(void* const* d_in, const int* in_sizes, int n_in,
                              void* d_out, int out_size) {
    const float* t  = (const float*)d_in[0];
    const float* W1 = (const float*)d_in[1];
    const float* b1 = (const float*)d_in[2];
    const float* W2 = (const float*)d_in[3];
    const float* b2 = (const float*)d_in[4];
    const float* W3 = (const float*)d_in[5];
    const float* b3 = (const float*)d_in[6];
    float* out = (float*)d_out;

    int n  = in_sizes[0];            // B*T = 131072
    int n4 = n / 4;                  // 32768 float4 samples
    int grid = (n4 + 511) / 512;     // 64 blocks, 1 float4 per thread

    haar_fused2_kernel<<<grid, 512>>>(
        (const float4*)t, W1, b1, W2, b2, W3, b3, (float4*)out, n4);
}